// round 3
// baseline (speedup 1.0000x reference)
#include <cuda_runtime.h>

// MeanConv: out = (1/7) * sum_{k in {3,5,7,9,11,13,15}} box_mean_k(x, replicate pad) * mask
// x: [4096,4096] fp32 (d_in[0]), mask: [4096,4096] fp32 (d_in[1]), out: fp32.
//
// Strategy: per-block 128-col strip, slide down 128 rows.
//  - SMEM ring buffer of 16 rows of horizontal PREFIX sums over the strip window
//    (width 128 + 2*7 halo, clamped at image borders -> replicate pad exact).
//  - Per-thread (one output column) 7 vertical running sums acc_k of the
//    horizontal window sums; at row r, acc_k covers rows [r-hk, r+hk].
//    Emit output FIRST, then update acc += h_k(r+1+hk) - h_k(r-hk) for r+1.
//  - out = sum_k acc_k / (7*k^2) * mask.

#define H_DIM 4096
#define W_DIM 4096
#define TW    128      // output columns per block
#define SH    128      // output rows per block
#define NTH   128      // threads per block
#define HALO  7
#define NROWVALS 142   // TW + 2*HALO raw values per row window
#define NPREF    143   // prefix entries P[0..142]
#define TWP      144   // padded row stride in smem
#define RING     16

__global__ __launch_bounds__(NTH)
void meanconv_kernel(const float* __restrict__ x,
                     const float* __restrict__ mask,
                     float* __restrict__ out)
{
    __shared__ float ring[RING][TWP];
    __shared__ float warp_sums[NTH / 32];

    const int t    = threadIdx.x;
    const int lane = t & 31;
    const int wrp  = t >> 5;
    const int c0   = blockIdx.x * TW;
    const int r0   = blockIdx.y * SH;
    const int j    = t + HALO;   // this thread's center position in the prefix row

    // ---- load one image row (clamped) and build its prefix sum into ring[slot] ----
    auto load_row = [&](int gr) {
        const int grc = min(max(gr, 0), H_DIM - 1);
        const float* __restrict__ row = x + (size_t)grc * W_DIM;

        const int i0 = 2 * t;
        const int i1 = 2 * t + 1;
        float e0 = 0.0f, e1 = 0.0f;
        if (i0 < NROWVALS) e0 = row[min(max(c0 - HALO + i0, 0), W_DIM - 1)];
        if (i1 < NROWVALS) e1 = row[min(max(c0 - HALO + i1, 0), W_DIM - 1)];

        float s = e0 + e1;
        float inc = s;
        #pragma unroll
        for (int d = 1; d < 32; d <<= 1) {
            float n = __shfl_up_sync(0xffffffffu, inc, d);
            if (lane >= d) inc += n;
        }
        if (lane == 31) warp_sums[wrp] = inc;
        __syncthreads();

        float off = 0.0f;
        #pragma unroll
        for (int ww = 0; ww < NTH / 32 - 1; ww++)
            if (ww < wrp) off += warp_sums[ww];
        const float excl = off + inc - s;   // exclusive prefix = sum of e[0..i0-1]

        const int slot = (gr + 2 * RING) & (RING - 1);
        if (i0 < NPREF) ring[slot][i0] = excl;        // P[i0]
        if (i1 < NPREF) ring[slot][i1] = excl + e0;   // P[i1]
        __syncthreads();
    };

    // ---- preload rows r0-7 .. r0+7 ----
    for (int gr = r0 - HALO; gr <= r0 + HALO; gr++) load_row(gr);

    const int KS[7] = {3, 5, 7, 9, 11, 13, 15};
    const float wgt[7] = {
        1.0f / (7.0f *   9.0f), 1.0f / (7.0f *  25.0f), 1.0f / (7.0f *  49.0f),
        1.0f / (7.0f *  81.0f), 1.0f / (7.0f * 121.0f), 1.0f / (7.0f * 169.0f),
        1.0f / (7.0f * 225.0f)
    };

    // ---- initialize vertical running sums: acc_k covers rows [r0-hk, r0+hk] ----
    float acc[7];
    #pragma unroll
    for (int ki = 0; ki < 7; ki++) {
        const int hk = KS[ki] >> 1;
        float a = 0.0f;
        #pragma unroll
        for (int d = -7; d <= 7; d++) {
            if (d < -hk || d > hk) continue;
            const int slot = (r0 + d + 2 * RING) & (RING - 1);
            a += ring[slot][j + hk + 1] - ring[slot][j - hk];
        }
        acc[ki] = a;
    }

    // ---- main sweep ----
    for (int r = r0; r < r0 + SH; r++) {
        load_row(r + HALO + 1);   // bring in row r+8 (overwrites slot of r-8)

        // 1) emit output for row r from the CURRENT window (centered at r)
        float sum = 0.0f;
        #pragma unroll
        for (int ki = 0; ki < 7; ki++)
            sum += wgt[ki] * acc[ki];

        const size_t idx = (size_t)r * W_DIM + (size_t)(c0 + t);
        out[idx] = sum * mask[idx];

        // 2) slide window down: acc_k now covers [r+1-hk, r+1+hk]
        #pragma unroll
        for (int ki = 0; ki < 7; ki++) {
            const int hk = KS[ki] >> 1;
            const int sa = (r + 1 + hk + 2 * RING) & (RING - 1);
            const int ss = (r - hk     + 2 * RING) & (RING - 1);
            const float ha = ring[sa][j + hk + 1] - ring[sa][j - hk];
            const float hs = ring[ss][j + hk + 1] - ring[ss][j - hk];
            acc[ki] += ha - hs;
        }
    }
}

extern "C" void kernel_launch(void* const* d_in, const int* in_sizes, int n_in,
                              void* d_out, int out_size)
{
    const float* x    = (const float*)d_in[0];
    const float* mask = (const float*)d_in[1];
    float* out        = (float*)d_out;

    dim3 grid(W_DIM / TW, H_DIM / SH);
    dim3 block(NTH);
    meanconv_kernel<<<grid, block>>>(x, mask, out);
}

// round 7
// speedup vs baseline: 1.6919x; 1.6919x over previous
#include <cuda_runtime.h>

// MeanConv: out = (1/7) * sum_{k in {3,5,7,9,11,13,15}} box_mean_k(x, replicate pad) * mask
//
// R4 = R3 resubmit (infra flake). Chunked production (8 rows per step, one warp
// scans one row) to amortize barriers and overlap the prefix-scan latency across
// warps. 256-wide strips, 32-slot ring of horizontal prefix rows, per-thread 7
// vertical running sums.

#define H_DIM 4096
#define W_DIM 4096
#define TW    256                  // output columns per block
#define NTH   256
#define SH    128                  // output rows per block
#define HALO  7
#define NROWVALS (TW + 2*HALO)     // 270 raw values per row window
#define NPREF    (NROWVALS + 1)    // 271 prefix entries
#define TWP      272               // padded smem row stride (floats)
#define RING     32
#define CHUNK    8

__device__ __forceinline__ int clampi(int v, int lo, int hi) { return min(max(v, lo), hi); }

__global__ __launch_bounds__(NTH)
void meanconv_kernel(const float* __restrict__ x,
                     const float* __restrict__ mask,
                     float* __restrict__ out)
{
    __shared__ float ring[RING][TWP];

    const int t    = threadIdx.x;
    const int lane = t & 31;
    const int wrp  = t >> 5;
    const int c0   = blockIdx.x * TW;
    const int r0   = blockIdx.y * SH;
    const int j    = t + HALO;     // this thread's center position in a prefix row

    // ---- cooperative coalesced raw load of nrows rows into ring slots ----
    auto raw_load = [&](int base_row, int nrows) {
        const int total = nrows * NROWVALS;
        for (int v = t; v < total; v += NTH) {
            const int row = (int)((unsigned)v / NROWVALS);
            const int col = v - row * NROWVALS;
            const int gr  = base_row + row;
            const int grc = clampi(gr, 0, H_DIM - 1);
            const int gc  = clampi(c0 - HALO + col, 0, W_DIM - 1);
            ring[gr & (RING - 1)][col] = x[(size_t)grc * W_DIM + gc];
        }
    };

    // ---- one warp converts raw row -> in-place prefix sums P[0..270] ----
    auto scan_row = [&](int gr) {
        float* __restrict__ row = ring[gr & (RING - 1)];
        const int base = lane * 9;           // lanes 0..29 cover 0..269
        float ps[9];
        float tot = 0.0f;
        if (base < NROWVALS) {
            float s = row[base];
            ps[0] = s;
            #pragma unroll
            for (int i = 1; i < 9; i++) { s += row[base + i]; ps[i] = s; }
            tot = s;
        }
        float inc = tot;                     // inclusive warp scan of lane totals
        #pragma unroll
        for (int d = 1; d < 32; d <<= 1) {
            float n = __shfl_up_sync(0xffffffffu, inc, d);
            if (lane >= d) inc += n;
        }
        const float excl = inc - tot;
        __syncwarp();                        // all raw reads done before overwrite
        if (lane == 0) row[0] = 0.0f;
        if (base < NROWVALS) {
            #pragma unroll
            for (int i = 0; i < 9; i++) row[base + i + 1] = excl + ps[i];
        }
    };

    // ---- preload: rows r0-8 .. r0+7 (16 rows; -8 unused but harmless) ----
    raw_load(r0 - 8, 16);
    __syncthreads();
    scan_row(r0 - 8 + wrp);
    scan_row(r0 + wrp);
    __syncthreads();

    // ---- init vertical running sums: acc[ki] covers rows [r0-hk, r0+hk] ----
    float acc[7];
    #pragma unroll
    for (int ki = 0; ki < 7; ki++) {
        const int hk = ki + 1;               // k = 2*hk+1
        float a = 0.0f;
        #pragma unroll
        for (int d = -7; d <= 7; d++) {
            if (d < -hk || d > hk) continue;
            const float* __restrict__ rp = &ring[(r0 + d) & (RING - 1)][j];
            a += rp[hk + 1] - rp[-hk];
        }
        acc[ki] = a;
    }

    // ---- main sweep: per chunk, produce 8 rows ahead, then consume 8 rows ----
    for (int c = 0; c < SH / CHUNK; c++) {
        const int prow = r0 + 8 + c * CHUNK;
        raw_load(prow, CHUNK);
        __syncthreads();
        scan_row(prow + wrp);
        __syncthreads();

        const int crow = r0 + c * CHUNK;
        size_t idx = (size_t)crow * W_DIM + (size_t)(c0 + t);

        #pragma unroll
        for (int rr = 0; rr < CHUNK; rr++) {
            const int r = crow + rr;

            // emit output for row r from current windows (centered at r)
            float s = acc[0] * (1.0f / (7.0f *   9.0f));
            s = fmaf(acc[1], 1.0f / (7.0f *  25.0f), s);
            s = fmaf(acc[2], 1.0f / (7.0f *  49.0f), s);
            s = fmaf(acc[3], 1.0f / (7.0f *  81.0f), s);
            s = fmaf(acc[4], 1.0f / (7.0f * 121.0f), s);
            s = fmaf(acc[5], 1.0f / (7.0f * 169.0f), s);
            s = fmaf(acc[6], 1.0f / (7.0f * 225.0f), s);
            out[idx] = s * mask[idx];

            // slide windows down one row
            #pragma unroll
            for (int ki = 0; ki < 7; ki++) {
                const int hk = ki + 1;
                const float* __restrict__ ra = &ring[(r + 1 + hk) & (RING - 1)][j];
                const float* __restrict__ rs = &ring[(r - hk)     & (RING - 1)][j];
                acc[ki] += (ra[hk + 1] - ra[-hk]) - (rs[hk + 1] - rs[-hk]);
            }
            idx += W_DIM;
        }
        // no barrier here: next raw_load writes slots (rows crow+16..crow+23,
        // aliasing crow-16..crow-9 mod RING), disjoint from this chunk's read
        // window (rows crow-7..crow+15).
    }
}

extern "C" void kernel_launch(void* const* d_in, const int* in_sizes, int n_in,
                              void* d_out, int out_size)
{
    const float* x    = (const float*)d_in[0];
    const float* mask = (const float*)d_in[1];
    float* out        = (float*)d_out;

    dim3 grid(W_DIM / TW, H_DIM / SH);
    dim3 block(NTH);
    meanconv_kernel<<<grid, block>>>(x, mask, out);
}

// round 8
// speedup vs baseline: 2.2590x; 1.3352x over previous
#include <cuda_runtime.h>

// MeanConv: out = (1/7) * sum_{k in {3,5,7,9,11,13,15}} box_mean_k(x, replicate pad) * mask
//
// R7: latency-hiding restructure.
//  - SH=64 -> grid 1024 (better SM balance / occupancy)
//  - per-warp row ownership: warp w loads row (prow+w) into registers (prefetched
//    one chunk early, overlapping the LDS-heavy consume), stores it, and scans it.
//    Raw->scan hazard is warp-private => __syncwarp; ONE __syncthreads per chunk.
//  - 32-slot ring of horizontal prefix rows; per-thread 7 vertical running sums.

#define H_DIM 4096
#define W_DIM 4096
#define TW    256
#define NTH   256
#define SH    64
#define HALO  7
#define NROWVALS (TW + 2*HALO)     // 270
#define TWP      272               // padded smem row stride (floats), >= 271
#define RING     32
#define CHUNK    8                 // rows per chunk == warps per block
#define NCHUNK   (SH / CHUNK)      // 8

__device__ __forceinline__ int clampi(int v, int lo, int hi) { return min(max(v, lo), hi); }

__global__ __launch_bounds__(NTH, 4)
void meanconv_kernel(const float* __restrict__ x,
                     const float* __restrict__ mask,
                     float* __restrict__ out)
{
    __shared__ float ring[RING][TWP];

    const int t    = threadIdx.x;
    const int lane = t & 31;
    const int wrp  = t >> 5;
    const int c0   = blockIdx.x * TW;
    const int r0   = blockIdx.y * SH;
    const int j    = t + HALO;     // this thread's center position in a prefix row

    // ---- warp w loads row (base_row + w), cols lane+32*i (clamped), into regs ----
    auto load_rows = [&](int base_row, float (&pf)[9]) {
        const int grc = clampi(base_row + wrp, 0, H_DIM - 1);
        const float* __restrict__ rowp = x + (size_t)grc * W_DIM;
        #pragma unroll
        for (int i = 0; i < 8; i++) {
            const int gc = clampi(c0 - HALO + lane + 32 * i, 0, W_DIM - 1);
            pf[i] = rowp[gc];
        }
        if (lane < NROWVALS - 256) {   // lane < 14
            const int gc = clampi(c0 - HALO + lane + 256, 0, W_DIM - 1);
            pf[8] = rowp[gc];
        }
    };

    // ---- warp w: STS raw row, warp-sync, in-place prefix scan (P[0..270]) ----
    auto commit_rows = [&](int base_row, const float (&pf)[9]) {
        float* __restrict__ row = ring[(base_row + wrp) & (RING - 1)];
        #pragma unroll
        for (int i = 0; i < 8; i++) row[lane + 32 * i] = pf[i];
        if (lane < NROWVALS - 256) row[lane + 256] = pf[8];
        __syncwarp();

        const int base = lane * 9;                 // lanes 0..29 cover 0..269
        float ps[9];
        float tot = 0.0f;
        if (base < NROWVALS) {
            float s = row[base];
            ps[0] = s;
            #pragma unroll
            for (int i = 1; i < 9; i++) { s += row[base + i]; ps[i] = s; }
            tot = s;
        }
        float inc = tot;
        #pragma unroll
        for (int d = 1; d < 32; d <<= 1) {
            float n = __shfl_up_sync(0xffffffffu, inc, d);
            if (lane >= d) inc += n;
        }
        const float excl = inc - tot;
        __syncwarp();                              // all raw reads done before overwrite
        if (lane == 0) row[0] = 0.0f;
        if (base < NROWVALS) {
            #pragma unroll
            for (int i = 0; i < 9; i++) row[base + i + 1] = excl + ps[i];
        }
    };

    float pf[9];

    // ---- preload rows r0-8 .. r0+7 (two chunks) ----
    load_rows(r0 - 8, pf);  commit_rows(r0 - 8, pf);
    load_rows(r0,     pf);  commit_rows(r0,     pf);
    load_rows(r0 + 8, pf);                         // prefetch chunk 0 produce rows
    __syncthreads();

    // ---- init vertical running sums: acc[ki] covers rows [r0-hk, r0+hk] ----
    float acc[7];
    #pragma unroll
    for (int ki = 0; ki < 7; ki++) {
        const int hk = ki + 1;                     // k = 2*hk+1
        float a = 0.0f;
        #pragma unroll
        for (int d = -7; d <= 7; d++) {
            if (d < -hk || d > hk) continue;
            const float* __restrict__ rp = &ring[(r0 + d) & (RING - 1)][j];
            a += rp[hk + 1] - rp[-hk];
        }
        acc[ki] = a;
    }

    // ---- main sweep: 1 barrier per chunk; gmem prefetch overlaps consume ----
    for (int c = 0; c < NCHUNK; c++) {
        const int prow = r0 + 8 + c * CHUNK;       // rows produced this chunk
        commit_rows(prow, pf);                     // STS + warp-local scan
        if (c + 1 < NCHUNK)
            load_rows(prow + CHUNK, pf);           // prefetch next chunk (hidden)
        __syncthreads();                           // scanned rows visible to all

        const int crow = r0 + c * CHUNK;
        size_t idx = (size_t)crow * W_DIM + (size_t)(c0 + t);

        #pragma unroll
        for (int rr = 0; rr < CHUNK; rr++) {
            const int r = crow + rr;

            float s = acc[0] * (1.0f / (7.0f *   9.0f));
            s = fmaf(acc[1], 1.0f / (7.0f *  25.0f), s);
            s = fmaf(acc[2], 1.0f / (7.0f *  49.0f), s);
            s = fmaf(acc[3], 1.0f / (7.0f *  81.0f), s);
            s = fmaf(acc[4], 1.0f / (7.0f * 121.0f), s);
            s = fmaf(acc[5], 1.0f / (7.0f * 169.0f), s);
            s = fmaf(acc[6], 1.0f / (7.0f * 225.0f), s);
            out[idx] = s * mask[idx];

            #pragma unroll
            for (int ki = 0; ki < 7; ki++) {
                const int hk = ki + 1;
                const float* __restrict__ ra = &ring[(r + 1 + hk) & (RING - 1)][j];
                const float* __restrict__ rs = &ring[(r - hk)     & (RING - 1)][j];
                acc[ki] += (ra[hk + 1] - ra[-hk]) - (rs[hk + 1] - rs[-hk]);
            }
            idx += W_DIM;
        }
        // no trailing barrier: next commit writes slots == rows (prow+8..prow+15)
        // aliasing (crow-16..crow-9) mod 32, disjoint from any in-flight consumer
        // window (>= crow-15..crow+15 given the per-iteration barrier bound).
    }
}

extern "C" void kernel_launch(void* const* d_in, const int* in_sizes, int n_in,
                              void* d_out, int out_size)
{
    const float* x    = (const float*)d_in[0];
    const float* mask = (const float*)d_in[1];
    float* out        = (float*)d_out;

    dim3 grid(W_DIM / TW, H_DIM / SH);
    dim3 block(NTH);
    meanconv_kernel<<<grid, block>>>(x, mask, out);
}